// round 11
// baseline (speedup 1.0000x reference)
#include <cuda_runtime.h>
#include <cuda_fp16.h>
#include <cstdint>

#define DIM      512
#define NLAT     128
#define NTOK     16
#define NBATCH   1024
#define NH       8
#define M_KV     (NBATCH*NLAT)   // 131072
#define M_Q      (NBATCH*NTOK)   // 16384
#define DIMDIM   (DIM*DIM)

// fp16 scratch (device globals: allocation-free, zero-initialized)
__device__ __half g_Q  [(size_t)M_Q  * DIM];
__device__ __half g_A  [(size_t)M_Q  * DIM];
__device__ __half g_x16[(size_t)M_Q  * DIM];
__device__ __half g_l16[(size_t)M_KV * DIM];
__device__ __half g_W16[4 * DIMDIM];        // Wq, Wk, Wv, Wo

// ---------------- fp32 -> fp16 staging ----------------
__global__ __launch_bounds__(256)
void f2h_x(const float4* __restrict__ in)
{
    const int i = blockIdx.x * 256 + threadIdx.x;
    if (i >= M_Q * DIM / 4) return;
    __half2* out = reinterpret_cast<__half2*>(g_x16);
    const float4 v = in[i];
    out[2*i] = __floats2half2_rn(v.x, v.y);
    out[2*i+1] = __floats2half2_rn(v.z, v.w);
}

__global__ __launch_bounds__(256)
void f2h_l(const float4* __restrict__ in, int i0, int iend)
{
    const int i = blockIdx.x * 256 + threadIdx.x + i0;
    if (i >= iend) return;
    const int row = i >> 7;                             // 128 float4 per 512-row
    if ((row & 127) > ((row >> 7) & 127)) return;       // latent never attended
    __half2* out = reinterpret_cast<__half2*>(g_l16);
    const float4 v = in[i];
    out[2*i] = __floats2half2_rn(v.x, v.y);
    out[2*i+1] = __floats2half2_rn(v.z, v.w);
}

__global__ __launch_bounds__(256)
void f2h_w4(const float4* __restrict__ a, const float4* __restrict__ b,
            const float4* __restrict__ c, const float4* __restrict__ d)
{
    const int i = blockIdx.x * 256 + threadIdx.x;      // 0 .. 4*65536-1
    if (i >= 4 * (DIMDIM / 4)) return;
    const int w = i >> 16, r = i & 65535;
    const float4* src = (w == 0) ? a : (w == 1) ? b : (w == 2) ? c : d;
    const float4 v = src[r];
    __half2* out = reinterpret_cast<__half2*>(g_W16) + (size_t)w * (DIMDIM / 2);
    out[2*r] = __floats2half2_rn(v.x, v.y);
    out[2*r+1] = __floats2half2_rn(v.z, v.w);
}

// ---------------- mma helpers ----------------
__device__ __forceinline__ void cpa16(uint32_t s, const void* g){
    asm volatile("cp.async.cg.shared.global [%0], [%1], 16;\n" :: "r"(s), "l"(g));
}
__device__ __forceinline__ void ldsm4(uint32_t& r0, uint32_t& r1, uint32_t& r2, uint32_t& r3,
                                      uint32_t addr){
    asm volatile("ldmatrix.sync.aligned.m8n8.x4.shared.b16 {%0,%1,%2,%3}, [%4];\n"
                 : "=r"(r0), "=r"(r1), "=r"(r2), "=r"(r3) : "r"(addr));
}
__device__ __forceinline__ void ldsm4t(uint32_t& r0, uint32_t& r1, uint32_t& r2, uint32_t& r3,
                                       uint32_t addr){
    asm volatile("ldmatrix.sync.aligned.m8n8.x4.trans.shared.b16 {%0,%1,%2,%3}, [%4];\n"
                 : "=r"(r0), "=r"(r1), "=r"(r2), "=r"(r3) : "r"(addr));
}
__device__ __forceinline__ void mma_f16(float c[4], const uint32_t a[4],
                                        uint32_t b0, uint32_t b1){
    asm volatile(
        "mma.sync.aligned.m16n8k16.row.col.f32.f16.f16.f32 "
        "{%0,%1,%2,%3}, {%4,%5,%6,%7}, {%8,%9}, {%0,%1,%2,%3};\n"
        : "+f"(c[0]), "+f"(c[1]), "+f"(c[2]), "+f"(c[3])
        : "r"(a[0]), "r"(a[1]), "r"(a[2]), "r"(a[3]), "r"(b0), "r"(b1));
}

// ---------------- Q / O projection GEMM ----------------
#define BM 64
#define BN 128
#define BK 64
#define AST   72
#define A_BUF (BM * AST)
#define B_BUF (BN * AST)
#define GEMM_SMEM_BYTES ((2 * A_BUF + 2 * B_BUF) * 2)   // 55296 B

template<int MODE>   // 0: Q proj (x16 -> g_Q), 3: out proj (g_A -> fp32 out + bias)
__global__ __launch_bounds__(128, 4)
void gemm512(const float* __restrict__ bias, float* __restrict__ outf, int y0)
{
    const int m0 = (blockIdx.y + y0) * BM;
    const int n0 = blockIdx.x * BN;

    const __half* __restrict__ Asrc = (MODE == 0) ? g_x16 : g_A;
    const __half* __restrict__ Wsrc = g_W16 + (size_t)MODE * DIMDIM;

    extern __shared__ __half sh[];
    const uint32_t sbase = (uint32_t)__cvta_generic_to_shared(sh);

    const int tid  = threadIdx.x;
    const int lane = tid & 31;
    const int warp = tid >> 5;
    const int wm   = (warp >> 1) * 32;
    const int wn   = (warp & 1)  * 64;

    float c[2][8][4];
    #pragma unroll
    for (int mi = 0; mi < 2; mi++)
        #pragma unroll
        for (int ni = 0; ni < 8; ni++)
            #pragma unroll
            for (int q = 0; q < 4; q++) c[mi][ni][q] = 0.f;

    auto gload = [&](int kt, int buf){
        const int k0 = kt * BK;
        #pragma unroll
        for (int p = 0; p < 4; p++){
            const int id = tid + p * 128;
            const int r = id >> 3, ck = (id & 7) * 8;
            cpa16(sbase + 2u * (buf * A_BUF + r * AST + ck),
                  Asrc + (size_t)(m0 + r) * DIM + k0 + ck);
        }
        #pragma unroll
        for (int p = 0; p < 8; p++){
            const int id = tid + p * 128;
            const int r = id >> 3, ck = (id & 7) * 8;
            cpa16(sbase + 2u * (2 * A_BUF + buf * B_BUF + r * AST + ck),
                  Wsrc + (size_t)(n0 + r) * DIM + k0 + ck);
        }
        asm volatile("cp.async.commit_group;\n");
    };

    const int lrow = (lane & 7) + ((lane >> 3) & 1) * 8;
    const int lksel = (lane & 16) ? 8 : 0;

    auto compute = [&](int buf){
        const uint32_t aoff = buf * A_BUF;
        const uint32_t boff = 2 * A_BUF + buf * B_BUF;
        #pragma unroll
        for (int ks = 0; ks < 4; ks++){
            const int kk = ks * 16 + lksel;
            uint32_t a[2][4], bb[4][4];
            #pragma unroll
            for (int mi = 0; mi < 2; mi++){
                const int row = wm + mi * 16 + lrow;
                ldsm4(a[mi][0], a[mi][1], a[mi][2], a[mi][3],
                      sbase + 2u * (aoff + row * AST + kk));
            }
            #pragma unroll
            for (int nip = 0; nip < 4; nip++){
                const int nrow = wn + nip * 16 + lrow;
                ldsm4(bb[nip][0], bb[nip][1], bb[nip][2], bb[nip][3],
                      sbase + 2u * (boff + nrow * AST + kk));
            }
            #pragma unroll
            for (int mi = 0; mi < 2; mi++)
                #pragma unroll
                for (int nip = 0; nip < 4; nip++){
                    mma_f16(c[mi][2 * nip    ], a[mi], bb[nip][0], bb[nip][2]);
                    mma_f16(c[mi][2 * nip + 1], a[mi], bb[nip][1], bb[nip][3]);
                }
        }
    };

    gload(0, 0);
    int buf = 0;
    #pragma unroll 1
    for (int kt = 0; kt < DIM / BK; ++kt){
        const bool more = (kt + 1 < DIM / BK);
        if (more) gload(kt + 1, buf ^ 1);
        if (more) { asm volatile("cp.async.wait_group 1;\n"); }
        else      { asm volatile("cp.async.wait_group 0;\n"); }
        __syncthreads();
        compute(buf);
        __syncthreads();
        buf ^= 1;
    }

    #pragma unroll
    for (int mi = 0; mi < 2; mi++){
        #pragma unroll
        for (int ni = 0; ni < 8; ni++){
            const int row = m0 + wm + mi * 16 + (lane >> 2);
            const int col = n0 + wn + ni * 8 + (lane & 3) * 2;
            if (MODE == 3){
                float2 bv = *reinterpret_cast<const float2*>(&bias[col]);
                float2 o0 = make_float2(c[mi][ni][0] + bv.x, c[mi][ni][1] + bv.y);
                float2 o1 = make_float2(c[mi][ni][2] + bv.x, c[mi][ni][3] + bv.y);
                *reinterpret_cast<float2*>(&outf[(size_t)row * DIM + col])       = o0;
                *reinterpret_cast<float2*>(&outf[(size_t)(row + 8) * DIM + col]) = o1;
            } else {
                __half2 h0 = __floats2half2_rn(c[mi][ni][0], c[mi][ni][1]);
                __half2 h1 = __floats2half2_rn(c[mi][ni][2], c[mi][ni][3]);
                *reinterpret_cast<__half2*>(&g_Q[(size_t)row * DIM + col])       = h0;
                *reinterpret_cast<__half2*>(&g_Q[(size_t)(row + 8) * DIM + col]) = h1;
            }
        }
    }
}

// ---------------- fused K+V projection + attention ----------------
// Tile t of group g holds ALL valid latents of 2 paired batches:
//   rows [0, t+1)      -> batch g*128+t        (latent j = row)
//   rows [t+1, 128)    -> batch g*128+126-t    (latent j = row-t-1)
//   t=63: rows [0,64) batch 63 only; t=64: rows [0,128) batch 127.
// Cols [n0, n0+128) = heads {2*bx, 2*bx+1}. After the KV mainloop the CTA
// runs attention for its 2 batches x 2 heads entirely in smem -> writes g_A.
__device__ __forceinline__ void maprow(int g, int t, int i, int& grow, bool& val){
    int bsel, j; val = true;
    if (t == 64){ bsel = 127; j = i; }
    else if (t == 63){ bsel = 63; j = i; val = (i < 64); }
    else if (i <= t){ bsel = t; j = i; }
    else { bsel = 126 - t; j = i - t - 1; }
    grow = ((g << 7) + bsel) * NLAT + j;
}

#define KAST  72
#define KA_CH (128 * KAST)
#define KSTG  (3 * KA_CH)
#define KV_SMEM_BYTES (3 * KSTG * 2)     // 165888 B

// post-mainloop smem layout (half offsets)
#define KSM_O 0                          // K tile 128 x 136
#define VSM_O 17408                      // V tile 128 x 136
#define QSM_O 34816                      // 4 x (16 x 72)
#define PSM_O 39424                      // 4 x (16 x 136)

__global__ __launch_bounds__(256, 1)
void kv_attn(int y0)
{
    const int n0 = blockIdx.x * 128;
    const int my = blockIdx.y + y0;
    const int g = my / 65;
    const int t = my - g * 65;

    extern __shared__ __half sh[];
    const uint32_t sb = (uint32_t)__cvta_generic_to_shared(sh);
    __shared__ float Rinv[4][16];

    const int tid = threadIdx.x, lane = tid & 31, warp = tid >> 5;
    const int wm = (warp >> 1) * 32;
    const int wn = (warp & 1) * 64;

    const int ck = (tid & 7) * 8;
    const int rbase = tid >> 3;
    const __half* abase[4]; bool aval[4];
    const __half* kbase[4];
    #pragma unroll
    for (int p = 0; p < 4; p++){
        int grow; bool v;
        maprow(g, t, rbase + 32 * p, grow, v);
        abase[p] = g_l16 + (size_t)grow * DIM + ck;
        aval[p] = v;
        kbase[p] = g_W16 + (size_t)DIMDIM + (size_t)(n0 + rbase + 32 * p) * DIM + ck;
    }

    float cK[2][8][4], cV[2][8][4];
    #pragma unroll
    for (int mi = 0; mi < 2; mi++)
        #pragma unroll
        for (int ni = 0; ni < 8; ni++)
            #pragma unroll
            for (int q = 0; q < 4; q++){ cK[mi][ni][q] = 0.f; cV[mi][ni][q] = 0.f; }

    auto load = [&](int c, int s){
        const int k0 = c * 64;
        const uint32_t so = (uint32_t)s * KSTG;
        #pragma unroll
        for (int p = 0; p < 4; p++){
            const int r = rbase + 32 * p;
            if (aval[p])
                cpa16(sb + 2u * (so + r * KAST + ck), abase[p] + k0);
            cpa16(sb + 2u * (so + KA_CH + r * KAST + ck), kbase[p] + k0);
            cpa16(sb + 2u * (so + 2 * KA_CH + r * KAST + ck), kbase[p] + DIMDIM + k0);
        }
        asm volatile("cp.async.commit_group;\n");
    };

    const int lrow = (lane & 7) + ((lane >> 3) & 1) * 8;
    const int lksel = (lane & 16) ? 8 : 0;

    auto compute = [&](int s){
        const uint32_t ao = (uint32_t)s * KSTG;
        #pragma unroll
        for (int ks = 0; ks < 4; ks++){
            const int kk = ks * 16 + lksel;
            uint32_t a[2][4];
            #pragma unroll
            for (int mi = 0; mi < 2; mi++)
                ldsm4(a[mi][0], a[mi][1], a[mi][2], a[mi][3],
                      sb + 2u * (ao + (wm + mi * 16 + lrow) * KAST + kk));
            uint32_t bq[4][4];
            #pragma unroll
            for (int nip = 0; nip < 4; nip++)
                ldsm4(bq[nip][0], bq[nip][1], bq[nip][2], bq[nip][3],
                      sb + 2u * (ao + KA_CH + (wn + nip * 16 + lrow) * KAST + kk));
            #pragma unroll
            for (int mi = 0; mi < 2; mi++)
                #pragma unroll
                for (int nip = 0; nip < 4; nip++){
                    mma_f16(cK[mi][2 * nip    ], a[mi], bq[nip][0], bq[nip][2]);
                    mma_f16(cK[mi][2 * nip + 1], a[mi], bq[nip][1], bq[nip][3]);
                }
            #pragma unroll
            for (int nip = 0; nip < 4; nip++)
                ldsm4(bq[nip][0], bq[nip][1], bq[nip][2], bq[nip][3],
                      sb + 2u * (ao + 2 * KA_CH + (wn + nip * 16 + lrow) * KAST + kk));
            #pragma unroll
            for (int mi = 0; mi < 2; mi++)
                #pragma unroll
                for (int nip = 0; nip < 4; nip++){
                    mma_f16(cV[mi][2 * nip    ], a[mi], bq[nip][0], bq[nip][2]);
                    mma_f16(cV[mi][2 * nip + 1], a[mi], bq[nip][1], bq[nip][3]);
                }
        }
    };

    load(0, 0); load(1, 1);
    #pragma unroll 1
    for (int c = 0; c < 8; c++){
        if (c < 7) { asm volatile("cp.async.wait_group 1;\n"); }
        else       { asm volatile("cp.async.wait_group 0;\n"); }
        __syncthreads();
        compute(c % 3);
        if (c < 6) load(c + 2, (c + 2) % 3);
    }
    __syncthreads();   // stage buffers dead; smem re-used below

    // ---- store K,V fragments to smem tiles (row stride 136) ----
    const int r4 = lane >> 2, cc = (lane & 3) * 2;
    #pragma unroll
    for (int mi = 0; mi < 2; mi++)
        #pragma unroll
        for (int ni = 0; ni < 8; ni++){
            const int row = wm + mi * 16 + r4;
            const int col = wn + ni * 8 + cc;
            *reinterpret_cast<__half2*>(&sh[KSM_O + row * 136 + col]) =
                __floats2half2_rn(cK[mi][ni][0], cK[mi][ni][1]);
            *reinterpret_cast<__half2*>(&sh[KSM_O + (row + 8) * 136 + col]) =
                __floats2half2_rn(cK[mi][ni][2], cK[mi][ni][3]);
            *reinterpret_cast<__half2*>(&sh[VSM_O + row * 136 + col]) =
                __floats2half2_rn(cV[mi][ni][0], cV[mi][ni][1]);
            *reinterpret_cast<__half2*>(&sh[VSM_O + (row + 8) * 136 + col]) =
                __floats2half2_rn(cV[mi][ni][2], cV[mi][ni][3]);
        }

    // ---- problem assignment: 4 (batch, head) problems x 2 warps ----
    const int p    = warp >> 1, wsub = warp & 1;
    const int pb   = p >> 1,    ph   = p & 1;
    const int h    = 2 * blockIdx.x + ph;
    int b_p = 0, r0_p = 0, L_p = 0;
    if (pb == 0){ b_p = g * 128 + ((t == 64) ? 127 : t); r0_p = 0; L_p = (t == 64) ? 128 : (t + 1); }
    else if (t < 63){ b_p = g * 128 + 126 - t; r0_p = t + 1; L_p = 127 - t; }

    // load Q (16 x 64) for this problem
    if (L_p > 0){
        #pragma unroll
        for (int q = 0; q < 2; q++){
            const int idx = lane + q * 32;            // 0..63
            const int row = wsub * 8 + (idx >> 3);
            const int c8 = (idx & 7) * 8;
            *reinterpret_cast<uint4*>(&sh[QSM_O + p * 1152 + row * 72 + c8]) =
                *reinterpret_cast<const uint4*>(&g_Q[(size_t)(b_p * 16 + row) * DIM + h * 64 + c8]);
        }
    }
    __syncthreads();

    const int ralign = r0_p & ~15;
    const int nch = (L_p > 0) ? ((r0_p + L_p - ralign + 15) >> 4) : 0;
    const uint32_t qoff = sb + 2u * (QSM_O + p * 1152);
    const uint32_t poff = sb + 2u * (PSM_O + p * 2176);

    // ---- S = Q K^T (P indexed by tile row; masked -> 0) ----
    if (L_p > 0){
        uint32_t aq[4][4];
        #pragma unroll
        for (int ks = 0; ks < 4; ks++)
            ldsm4(aq[ks][0], aq[ks][1], aq[ks][2], aq[ks][3],
                  qoff + 2u * (lrow * 72 + ks * 16 + lksel));
        #pragma unroll 1
        for (int c = wsub; c < nch; c += 2){
            const int rb = ralign + c * 16;
            float c0[4] = {0,0,0,0}, c1[4] = {0,0,0,0};
            #pragma unroll
            for (int ks = 0; ks < 4; ks++){
                uint32_t bk[4];
                ldsm4(bk[0], bk[1], bk[2], bk[3],
                      sb + 2u * (KSM_O + (rb + lrow) * 136 + ph * 64 + ks * 16 + lksel));
                mma_f16(c0, aq[ks], bk[0], bk[2]);
                mma_f16(c1, aq[ks], bk[1], bk[3]);
            }
            #pragma unroll
            for (int tb = 0; tb < 2; tb++){
                const float* cs = tb ? c1 : c0;
                const int j0 = rb + tb * 8 + cc;
                const bool v0 = (j0     >= r0_p) && (j0     < r0_p + L_p);
                const bool v1 = (j0 + 1 >= r0_p) && (j0 + 1 < r0_p + L_p);
                *reinterpret_cast<__half2*>(&sh[PSM_O + p * 2176 + r4 * 136 + j0]) =
                    __floats2half2_rn(v0 ? cs[0] * 0.125f : 0.f, v1 ? cs[1] * 0.125f : 0.f);
                *reinterpret_cast<__half2*>(&sh[PSM_O + p * 2176 + (r4 + 8) * 136 + j0]) =
                    __floats2half2_rn(v0 ? cs[2] * 0.125f : 0.f, v1 ? cs[3] * 0.125f : 0.f);
            }
        }
    }
    __syncthreads();

    // ---- softmax over cols [r0, r0+L) ----
    if (L_p > 0){
        for (int i = wsub; i < 16; i += 2){
            float m = -1e30f;
            for (int jj = r0_p + lane; jj < r0_p + L_p; jj += 32)
                m = fmaxf(m, __half2float(sh[PSM_O + p * 2176 + i * 136 + jj]));
            #pragma unroll
            for (int o = 16; o > 0; o >>= 1) m = fmaxf(m, __shfl_xor_sync(0xffffffffu, m, o));
            float sum = 0.f;
            for (int jj = r0_p + lane; jj < r0_p + L_p; jj += 32){
                const float e = __expf(__half2float(sh[PSM_O + p * 2176 + i * 136 + jj]) - m);
                sh[PSM_O + p * 2176 + i * 136 + jj] = __float2half(e);
                sum += e;
            }
            #pragma unroll
            for (int o = 16; o > 0; o >>= 1) sum += __shfl_xor_sync(0xffffffffu, sum, o);
            if (lane == 0) Rinv[p][i] = 1.f / sum;
        }
    }
    __syncthreads();

    // ---- O = P V (warp covers dh cols [wsub*32, wsub*32+32)) ----
    if (L_p > 0){
        float o[4][4];
        #pragma unroll
        for (int q = 0; q < 4; q++)
            #pragma unroll
            for (int r = 0; r < 4; r++) o[q][r] = 0.f;
        #pragma unroll 1
        for (int c = 0; c < nch; c++){
            const int rb = ralign + c * 16;
            uint32_t ap_[4], bv0[4], bv1[4];
            ldsm4 (ap_[0], ap_[1], ap_[2], ap_[3], poff + 2u * (lrow * 136 + rb + lksel));
            ldsm4t(bv0[0], bv0[1], bv0[2], bv0[3],
                   sb + 2u * (VSM_O + (rb + lrow) * 136 + ph * 64 + wsub * 32 + lksel));
            ldsm4t(bv1[0], bv1[1], bv1[2], bv1[3],
                   sb + 2u * (VSM_O + (rb + lrow) * 136 + ph * 64 + wsub * 32 + 16 + lksel));
            mma_f16(o[0], ap_, bv0[0], bv0[1]);
            mma_f16(o[1], ap_, bv0[2], bv0[3]);
            mma_f16(o[2], ap_, bv1[0], bv1[1]);
            mma_f16(o[3], ap_, bv1[2], bv1[3]);
        }
        const float ri0 = Rinv[p][r4], ri1 = Rinv[p][r4 + 8];
        __half2* A2 = reinterpret_cast<__half2*>(g_A);
        #pragma unroll
        for (int blk = 0; blk < 4; blk++){
            const int d = h * 64 + wsub * 32 + blk * 8 + cc;
            A2[((size_t)(b_p * 16 + r4) * DIM + d) >> 1] =
                __floats2half2_rn(o[blk][0] * ri0, o[blk][1] * ri0);
            A2[((size_t)(b_p * 16 + r4 + 8) * DIM + d) >> 1] =
                __floats2half2_rn(o[blk][2] * ri1, o[blk][3] * ri1);
        }
    }
}

extern "C" void kernel_launch(void* const* d_in, const int* in_sizes, int n_in,
                              void* d_out, int out_size)
{
    (void)in_sizes; (void)n_in; (void)out_size;
    const float* x  = (const float*)d_in[0];
    const float* l  = (const float*)d_in[1];
    const float* Wq = (const float*)d_in[2];
    const float* Wk = (const float*)d_in[3];
    const float* Wv = (const float*)d_in[4];
    const float* Wo = (const float*)d_in[5];
    const float* bo = (const float*)d_in[6];
    float* out = (float*)d_out;

    static cudaStream_t s1 = nullptr, s2 = nullptr;
    static cudaEvent_t eS, eQ, eL0, eL1, eKV0, eKV1, eO0, eO1;
    static bool init_done = false;
    if (!init_done){
        cudaFuncSetAttribute(gemm512<0>, cudaFuncAttributeMaxDynamicSharedMemorySize, GEMM_SMEM_BYTES);
        cudaFuncSetAttribute(gemm512<3>, cudaFuncAttributeMaxDynamicSharedMemorySize, GEMM_SMEM_BYTES);
        cudaFuncSetAttribute(kv_attn,   cudaFuncAttributeMaxDynamicSharedMemorySize, KV_SMEM_BYTES);
        cudaStreamCreateWithFlags(&s1, cudaStreamNonBlocking);
        cudaStreamCreateWithFlags(&s2, cudaStreamNonBlocking);
        cudaEventCreateWithFlags(&eS,   cudaEventDisableTiming);
        cudaEventCreateWithFlags(&eQ,   cudaEventDisableTiming);
        cudaEventCreateWithFlags(&eL0,  cudaEventDisableTiming);
        cudaEventCreateWithFlags(&eL1,  cudaEventDisableTiming);
        cudaEventCreateWithFlags(&eKV0, cudaEventDisableTiming);
        cudaEventCreateWithFlags(&eKV1, cudaEventDisableTiming);
        cudaEventCreateWithFlags(&eO0,  cudaEventDisableTiming);
        cudaEventCreateWithFlags(&eO1,  cudaEventDisableTiming);
        init_done = true;
    }

    const int n4x = M_Q  * DIM / 4;
    const int n4l = M_KV * DIM / 4;
    const int n4l_half = n4l / 2;

    // fork side streams off the capture-origin (default) stream
    cudaEventRecord(eS, 0);
    cudaStreamWaitEvent(s1, eS, 0);
    cudaStreamWaitEvent(s2, eS, 0);

    // s1: weights + x staging, then Q projection
    f2h_w4<<<(4 * DIMDIM / 4 + 255) / 256, 256, 0, s1>>>(
        (const float4*)Wq, (const float4*)Wk, (const float4*)Wv, (const float4*)Wo);
    f2h_x<<<(n4x + 255) / 256, 256, 0, s1>>>((const float4*)x);
    gemm512<0><<<dim3(DIM / BN, M_Q / BM), 128, GEMM_SMEM_BYTES, s1>>>(nullptr, nullptr, 0);
    cudaEventRecord(eQ, s1);

    // s0: l half 0
    f2h_l<<<(n4l_half + 255) / 256, 256>>>((const float4*)l, 0, n4l_half);
    cudaEventRecord(eL0, 0);

    // s2: l half 1 (overlaps KV0)
    cudaStreamWaitEvent(s2, eL0, 0);
    f2h_l<<<(n4l_half + 255) / 256, 256, 0, s2>>>((const float4*)l, n4l_half, n4l);
    cudaEventRecord(eL1, s2);

    // s0: fused KV+attn groups 0-3 (needs W+Q via eQ, l0 in-stream), then 4-7
    cudaStreamWaitEvent(0, eQ, 0);
    kv_attn<<<dim3(4, 260), 256, KV_SMEM_BYTES>>>(0);
    cudaEventRecord(eKV0, 0);
    cudaStreamWaitEvent(0, eL1, 0);
    kv_attn<<<dim3(4, 260), 256, KV_SMEM_BYTES>>>(260);
    cudaEventRecord(eKV1, 0);

    // s1: out-proj for batches 0-511 (g_A written by KV0)
    cudaStreamWaitEvent(s1, eKV0, 0);
    gemm512<3><<<dim3(DIM / BN, 128), 128, GEMM_SMEM_BYTES, s1>>>(bo, out, 0);
    cudaEventRecord(eO0, s1);

    // s2: out-proj for batches 512-1023 (g_A written by KV1)
    cudaStreamWaitEvent(s2, eKV1, 0);
    gemm512<3><<<dim3(DIM / BN, 128), 128, GEMM_SMEM_BYTES, s2>>>(bo, out, 128);
    cudaEventRecord(eO1, s2);

    // join back onto the origin stream
    cudaStreamWaitEvent(0, eO0, 0);
    cudaStreamWaitEvent(0, eO1, 0);
}